// round 17
// baseline (speedup 1.0000x reference)
#include <cuda_runtime.h>
#include <cstdint>

// CostVolume2D: out[n, dy*9+dx, h, w] = mean_c f1[n,c,h,w] * f2pad[n,c,h+dy,w+dx]
// N=8, C=128, H=96, W=224, D=4 -> 81 channels. fp32.
//
// R17 = R8 (best: 134.2us) with the STAGING PATH swapped to cp.async.bulk
// (UBLKCP) + mbarrier complete_tx: 136 row-copies per chunk (1-2 per thread)
// instead of 1280 per-thread LDGSTS. OOB rows / edge 16B segments are
// zero-filled ONCE in the prologue (bulk copies never write them). Data wait
// is an acquire mbarrier try_wait -> only ONE __syncthreads per chunk.
// Compute body, double-buffer scheme and ordering are R8-verbatim.

#define N_ 8
#define C_ 128
#define H_ 96
#define W_ 224

constexpr int TH = 16;
constexpr int TW = 32;
constexpr int DG = 3;          // dy offsets per block (9 split across gridDim.z)
constexpr int CCH = 4;         // channels per pipeline stage
constexpr int NCHUNK = C_ / CCH;   // 32
constexpr int THREADS = 128;   // blockDim = (8,16)
constexpr int RW  = TW + 8;    // 40 padded row
constexpr int S2R = TH + 2;    // 18 rows
constexpr int F1_ROWS = CCH * TH;    // 64 rows x 128 B
constexpr int F2_ROWS = CCH * S2R;   // 72 rows x 160 B
constexpr int S1BYTES = CCH * TH * TW * 4;    // 8192 per buffer
constexpr int S2BYTES = CCH * S2R * RW * 4;   // 11520 per buffer

__device__ __forceinline__ void bulk_g2s(uint32_t dst, const void* src,
                                         uint32_t bytes, uint32_t mbar) {
    asm volatile(
        "cp.async.bulk.shared::cluster.global.mbarrier::complete_tx::bytes "
        "[%0], [%1], %2, [%3];"
        :: "r"(dst), "l"(src), "r"(bytes), "r"(mbar) : "memory");
}
__device__ __forceinline__ void mbar_init(uint32_t mbar, uint32_t cnt) {
    asm volatile("mbarrier.init.shared.b64 [%0], %1;"
                 :: "r"(mbar), "r"(cnt) : "memory");
}
__device__ __forceinline__ void mbar_arrive_tx(uint32_t mbar, uint32_t tx) {
    asm volatile("mbarrier.arrive.expect_tx.shared.b64 _, [%0], %1;"
                 :: "r"(mbar), "r"(tx) : "memory");
}
__device__ __forceinline__ void mbar_arrive(uint32_t mbar) {
    asm volatile("mbarrier.arrive.shared.b64 _, [%0];"
                 :: "r"(mbar) : "memory");
}
__device__ __forceinline__ void mbar_wait(uint32_t mbar, uint32_t parity) {
    asm volatile(
        "{\n\t"
        ".reg .pred P;\n"
        "WAIT_%=:\n\t"
        "mbarrier.try_wait.parity.acquire.cta.shared::cta.b64 P, [%0], %1, 0x989680;\n\t"
        "@P bra.uni DONE_%=;\n\t"
        "bra.uni WAIT_%=;\n"
        "DONE_%=:\n\t"
        "}"
        :: "r"(mbar), "r"(parity) : "memory");
}
__device__ __forceinline__ void fence_proxy_async_cta() {
    asm volatile("fence.proxy.async.shared::cta;" ::: "memory");
}

__device__ __forceinline__ uint64_t pk2(float lo, float hi) {
    uint64_t r; asm("mov.b64 %0, {%1, %2};" : "=l"(r) : "f"(lo), "f"(hi)); return r;
}
__device__ __forceinline__ void fma2(uint64_t& acc, uint64_t a, uint64_t b) {
    asm("fma.rn.f32x2 %0, %1, %2, %0;" : "+l"(acc) : "l"(a), "l"(b));
}
__device__ __forceinline__ void upk(uint64_t v, float& lo, float& hi) {
    asm("mov.b64 {%0, %1}, %2;" : "=f"(lo), "=f"(hi) : "l"(v));
}

__global__ __launch_bounds__(THREADS, 3)
void costvol_kernel(const float* __restrict__ f1,
                    const float* __restrict__ f2,
                    float* __restrict__ out)
{
    __shared__ __align__(16) float s1[2][CCH][TH][TW];   // 16 KB
    __shared__ __align__(16) float s2[2][CCH][S2R][RW];  // 23 KB
    __shared__ __align__(16) uint64_t mbar[2];

    const int tx  = threadIdx.x;          // 0..7
    const int ty  = threadIdx.y;          // 0..15
    const int tid = ty * 8 + tx;

    const int tile_x = blockIdx.x * TW;
    const int tile_y = blockIdx.y * TH;
    const int g      = blockIdx.z % 3;
    const int n      = blockIdx.z / 3;    // n-major z for L2 locality
    const int dy0    = 3 * g;

    const float* f1n = f1 + (size_t)n * C_ * H_ * W_;
    const float* f2n = f2 + (size_t)n * C_ * H_ * W_;

    const uint32_t s1b = (uint32_t)__cvta_generic_to_shared(&s1[0][0][0][0]);
    const uint32_t s2b = (uint32_t)__cvta_generic_to_shared(&s2[0][0][0][0]);
    const uint32_t mb0 = (uint32_t)__cvta_generic_to_shared(&mbar[0]);
    const uint32_t mb1 = (uint32_t)__cvta_generic_to_shared(&mbar[1]);

    // ---- per-thread bulk-copy jobs (1 primary + optional secondary) ----
    // idx < 64: f1 row (c = idx/16, r = idx%16), 128 B, always valid.
    // idx >= 64: f2 padded row j = idx-64 (c = j/18, r = j%18), 160 B nominal;
    //   OOB row -> 0 B (pre-zeroed); left/right tile edge -> 144 B.
    int  joff[2];     // gmem float offset within the chunk's channel block
    uint32_t jdst[2]; // smem byte offset within buffer-0 region
    uint32_t jbyt[2]; // bytes (0 = skip)
    bool jisf1[2];
    int  njob = 1 + (tid < F1_ROWS + F2_ROWS - THREADS ? 1 : 0);  // tids 0..7 get 2
#pragma unroll
    for (int s = 0; s < 2; s++) {
        int idx = (s == 0) ? tid : tid + THREADS;
        if (s == 1 && idx >= F1_ROWS + F2_ROWS) { jbyt[s] = 0; joff[s] = 0; jdst[s] = 0; jisf1[s] = true; continue; }
        if (idx < F1_ROWS) {
            int c = idx >> 4, r = idx & 15;
            joff[s]  = (c * H_ + tile_y + r) * W_ + tile_x;
            jdst[s]  = (uint32_t)(((c * TH + r) * TW) * 4);
            jbyt[s]  = 128;
            jisf1[s] = true;
        } else {
            int j = idx - F1_ROWS;
            int c = j / S2R, r = j - c * S2R;
            int gy = tile_y + dy0 - 4 + r;
            jisf1[s] = false;
            if ((unsigned)gy >= (unsigned)H_) {
                jbyt[s] = 0; joff[s] = 0; jdst[s] = 0;
            } else {
                int col = tile_x - 4;
                uint32_t doff = (uint32_t)(((c * S2R + r) * RW) * 4);
                uint32_t b = 160;
                if (tile_x == 0)            { col = 0; doff += 16; b = 144; }
                else if (tile_x + 36 > W_)  { b = 144; }
                joff[s] = (c * H_ + gy) * W_ + col;
                jdst[s] = doff;
                jbyt[s] = b;
            }
        }
    }
    const uint32_t mytx = jbyt[0] + (njob > 1 ? jbyt[1] : 0);

    // ---- init barriers ----
    if (tid == 0) { mbar_init(mb0, THREADS); mbar_init(mb1, THREADS); }
    fence_proxy_async_cta();

    // ---- zero-fill OOB rows + edge 16B segments in BOTH buffers (once) ----
    for (int idx = tid; idx < 2 * F2_ROWS; idx += THREADS) {
        int b = idx / F2_ROWS, j = idx - b * F2_ROWS;
        int c = j / S2R, r = j - c * S2R;
        int gy = tile_y + dy0 - 4 + r;
        float4 z = make_float4(0.f, 0.f, 0.f, 0.f);
        float* row = &s2[b][c][r][0];
        if ((unsigned)gy >= (unsigned)H_) {
#pragma unroll
            for (int q = 0; q < 10; q++)
                *reinterpret_cast<float4*>(row + q * 4) = z;
        } else {
            if (tile_x == 0)           *reinterpret_cast<float4*>(row) = z;
            if (tile_x + TW + 4 > W_)  *reinterpret_cast<float4*>(row + 36) = z;
        }
    }
    __syncthreads();   // barriers initialized + zeros visible before staging

    // ---- staging: one arrive + <=2 bulk copies per thread ----
    auto stage = [&](int buf, int cb) {
        const float* b1 = f1n + (size_t)cb * CCH * H_ * W_;
        const float* b2 = f2n + (size_t)cb * CCH * H_ * W_;
        const uint32_t mb = buf ? mb1 : mb0;
        if (mytx) mbar_arrive_tx(mb, mytx); else mbar_arrive(mb);
#pragma unroll
        for (int s = 0; s < 2; s++) {
            if (s >= njob || jbyt[s] == 0) continue;
            uint32_t dst = jisf1[s]
                ? s1b + (uint32_t)buf * S1BYTES + jdst[s]
                : s2b + (uint32_t)buf * S2BYTES + jdst[s];
            const float* src = (jisf1[s] ? b1 : b2) + joff[s];
            bulk_g2s(dst, src, jbyt[s], mb);
        }
    };

    // packed accumulators: pp=0 -> pixels (0,1), pp=1 -> (2,3)
    uint64_t acc0[DG][9], acc1[DG][9];
#pragma unroll
    for (int d = 0; d < DG; d++)
#pragma unroll
        for (int x = 0; x < 9; x++) { acc0[d][x] = 0ull; acc1[d][x] = 0ull; }

    // ---- pipeline prologue (depth 2) ----
    stage(0, 0);
    stage(1, 1);

    for (int cb = 0; cb < NCHUNK; cb++) {
        const int buf = cb & 1;
        mbar_wait(buf ? mb1 : mb0, (cb >> 1) & 1);   // block-global: no extra sync

#pragma unroll
        for (int c = 0; c < CCH; c++) {
            uint64_t a01, a23;
            {
                float4 av = *reinterpret_cast<const float4*>(&s1[buf][c][ty][tx * 4]);
                a01 = pk2(av.x, av.y);
                a23 = pk2(av.z, av.w);
            }
#pragma unroll
            for (int dyi = 0; dyi < DG; dyi++) {
                const float* row = &s2[buf][c][ty + dyi][tx * 4];
                float4 b0 = *reinterpret_cast<const float4*>(row);
                float4 b1 = *reinterpret_cast<const float4*>(row + 4);
                float4 b2 = *reinterpret_cast<const float4*>(row + 8);
                uint64_t pe0 = pk2(b0.x, b0.y);
                uint64_t pe1 = pk2(b0.z, b0.w);
                uint64_t pe2 = pk2(b1.x, b1.y);
                uint64_t pe3 = pk2(b1.z, b1.w);
                uint64_t pe4 = pk2(b2.x, b2.y);
                uint64_t pe5 = pk2(b2.z, b2.w);
                uint64_t po0 = pk2(b0.y, b0.z);
                uint64_t po1 = pk2(b0.w, b1.x);
                uint64_t po2 = pk2(b1.y, b1.z);
                uint64_t po3 = pk2(b1.w, b2.x);
                uint64_t po4 = pk2(b2.y, b2.z);

                uint64_t pr[11] = {pe0, po0, pe1, po1, pe2, po2,
                                   pe3, po3, pe4, po4, pe5};
#pragma unroll
                for (int dx = 0; dx < 9; dx++) {
                    fma2(acc0[dyi][dx], a01, pr[dx]);
                    fma2(acc1[dyi][dx], a23, pr[dx + 2]);
                }
            }
        }

        __syncthreads();   // all warps done reading buf before restaging it
        if (cb + 2 < NCHUNK) stage(buf, cb + 2);
    }

    // ---- epilogue ----
    const float inv = 1.0f / (float)C_;
    float* outn = out + (size_t)n * 81 * H_ * W_;
    const int y = tile_y + ty;
    const int x = tile_x + tx * 4;
#pragma unroll
    for (int dyi = 0; dyi < DG; dyi++)
#pragma unroll
        for (int dx = 0; dx < 9; dx++) {
            int k = (dy0 + dyi) * 9 + dx;
            float v0, v1, v2, v3;
            upk(acc0[dyi][dx], v0, v1);
            upk(acc1[dyi][dx], v2, v3);
            float4 v = make_float4(v0 * inv, v1 * inv, v2 * inv, v3 * inv);
            *reinterpret_cast<float4*>(outn + ((size_t)k * H_ + y) * W_ + x) = v;
        }
}

extern "C" void kernel_launch(void* const* d_in, const int* in_sizes, int n_in,
                              void* d_out, int out_size)
{
    const float* f1 = (const float*)d_in[0];
    const float* f2 = (const float*)d_in[1];
    float* out = (float*)d_out;

    dim3 block(8, 16);                      // 128 threads
    dim3 grid(W_ / TW, H_ / TH, N_ * 3);    // 7 x 6 x 24 = 1008
    costvol_kernel<<<grid, block>>>(f1, f2, out);
}